// round 8
// baseline (speedup 1.0000x reference)
#include <cuda_runtime.h>
#include <cstdint>
#include <cstddef>

// ---------------------------------------------------------------------------
// GRU stack: 4 layers (256 -> 256), B=128, T=384, reset_after=True (Keras).
// Phase A (per layer): xp = X @ W + b_in   (fp32 GEMM, scalar FFMA, dbl-buffer)
// Phase B (per layer): persistent scan, 8-CTA clusters per batch tile.
//   h exchange = PULL model: producers publish their 1KB slice locally +
//   remote-arrive "full"; each consumer warp pull-copies its peer's slice via
//   ld.shared::cluster, then remote-arrives "empty". 16 msgs/CTA/step.
// ---------------------------------------------------------------------------

#define BATCH   128
#define T_STEPS 384
#define UNITS   256
#define G3      768
#define MROWS   (BATCH * T_STEPS)   // 49152

__device__ float g_xp[MROWS * G3];      // [B*T, 768] input projections
__device__ float g_hseq[MROWS * UNITS]; // [B*T, 256] hidden sequence

// ---------------------------------------------------------------------------
typedef unsigned long long ull;

__device__ __forceinline__ ull p2(float x, float y) {
    ull d; asm("mov.b64 %0, {%1, %2};" : "=l"(d) : "f"(x), "f"(y)); return d;
}
__device__ __forceinline__ ull p1(float x) {
    ull d; asm("mov.b64 %0, {%1, %1};" : "=l"(d) : "f"(x)); return d;
}
__device__ __forceinline__ void fma2(ull& acc, ull a, ull b) {
    asm("fma.rn.f32x2 %0, %1, %2, %0;" : "+l"(acc) : "l"(a), "l"(b));
}
__device__ __forceinline__ void add2(ull& acc, ull a) {
    asm("add.rn.f32x2 %0, %1, %0;" : "+l"(acc) : "l"(a));
}
__device__ __forceinline__ float2 unp2(ull d) {
    float2 v; asm("mov.b64 {%0, %1}, %2;" : "=f"(v.x), "=f"(v.y) : "l"(d)); return v;
}

// ---------------------------------------------------------------------------
__device__ __forceinline__ uint32_t smem_u32(const void* p) {
    uint32_t a;
    asm("{ .reg .u64 t; cvta.to.shared.u64 t, %1; cvt.u32.u64 %0, t; }"
        : "=r"(a) : "l"(p));
    return a;
}
__device__ __forceinline__ uint32_t mapa_u32(uint32_t a, uint32_t rank) {
    uint32_t r;
    asm("mapa.shared::cluster.u32 %0, %1, %2;" : "=r"(r) : "r"(a), "r"(rank));
    return r;
}
__device__ __forceinline__ void mbar_init(uint32_t a, uint32_t cnt) {
    asm volatile("mbarrier.init.shared.b64 [%0], %1;" :: "r"(a), "r"(cnt) : "memory");
}
// remote arrive with explicit release.cluster semantics (publishes prior
// smem writes of this CTA, ordered by the preceding bar.sync)
__device__ __forceinline__ void mbar_arrive_remote(uint32_t a) {
    asm volatile("mbarrier.arrive.release.cluster.shared::cluster.b64 _, [%0];"
                 :: "r"(a) : "memory");
}
// deadman wait: pure spin (fast-path TRYWAIT ~90cyc), bounded; returns success.
__device__ __forceinline__ bool mbar_try_wait(uint32_t a, int parity) {
    unsigned ok = 0;
    for (int i = 0; i < 200000; i++) {
        asm volatile(
            "{\n\t.reg .pred P;\n\t"
            "mbarrier.try_wait.parity.acquire.cluster.shared::cta.b64 P, [%1], %2;\n\t"
            "selp.u32 %0, 1, 0, P;\n\t}"
            : "=r"(ok) : "r"(a), "r"((unsigned)parity) : "memory");
        if (ok) return true;
    }
    return false;
}
// DSMEM vector load (peer CTA smem)
__device__ __forceinline__ float4 ld_dsmem4(uint32_t a) {
    float4 v;
    asm volatile("ld.shared::cluster.v4.f32 {%0, %1, %2, %3}, [%4];"
        : "=f"(v.x), "=f"(v.y), "=f"(v.z), "=f"(v.w) : "r"(a));
    return v;
}
#define CLUSTER_SYNC_() do {                                          \
    asm volatile("barrier.cluster.arrive.aligned;" ::: "memory");     \
    asm volatile("barrier.cluster.wait.aligned;" ::: "memory");       \
} while (0)

__device__ __forceinline__ float sigm_(float x) {
    return 1.f / (1.f + __expf(-x));
}
__device__ __forceinline__ float tanh_(float x) {
    float s = 1.f / (1.f + __expf(-2.f * x));
    return 2.f * s - 1.f;
}

// ---------------------------------------------------------------------------
// SGEMM: C[M=49152, N=768] = A[M,256] @ W[256,768] + bias_in[768]
// (Proven R2/R5 version: 359us, fma=67.5%, regs=125.)
// ---------------------------------------------------------------------------
__global__ __launch_bounds__(256, 2) void gemm_kernel(
    const float* __restrict__ X,
    const float* __restrict__ W,
    const float* __restrict__ bin,
    int use_x)
{
    const int K = 256, N = G3;
    const float* A = use_x ? X : g_hseq;

    __shared__ float As[2][8][128];
    __shared__ float Bs[2][8][128];

    int tid = threadIdx.x;
    int tx = tid & 15;
    int ty = tid >> 4;
    int bm = blockIdx.y * 128;
    int bn = blockIdx.x * 128;

    float acc[8][8];
#pragma unroll
    for (int i = 0; i < 8; i++)
#pragma unroll
        for (int j = 0; j < 8; j++) acc[i][j] = 0.f;

    int arow = tid >> 1;
    int acol = (tid & 1) * 4;
    int brow = tid >> 5;
    int bcol = (tid & 31) * 4;

    const float* Ap = A + (size_t)(bm + arow) * K + acol;
    const float* Wp = W + (size_t)brow * N + bn + bcol;

    {
        float4 a4 = *(const float4*)(Ap);
        float4 b4 = *(const float4*)(Wp);
        As[0][acol + 0][arow] = a4.x;
        As[0][acol + 1][arow] = a4.y;
        As[0][acol + 2][arow] = a4.z;
        As[0][acol + 3][arow] = a4.w;
        *(float4*)&Bs[0][brow][bcol] = b4;
    }
    __syncthreads();

    int buf = 0;
    for (int k0 = 8; k0 <= K; k0 += 8) {
        float4 a4n, b4n;
        if (k0 < K) {
            a4n = *(const float4*)(Ap + k0);
            b4n = *(const float4*)(Wp + (size_t)k0 * N);
        }
#pragma unroll
        for (int kk = 0; kk < 8; kk++) {
            float ra[8], rb[8];
            *(float4*)(ra)     = *(const float4*)&As[buf][kk][ty * 4];
            *(float4*)(ra + 4) = *(const float4*)&As[buf][kk][64 + ty * 4];
            *(float4*)(rb)     = *(const float4*)&Bs[buf][kk][tx * 4];
            *(float4*)(rb + 4) = *(const float4*)&Bs[buf][kk][64 + tx * 4];
#pragma unroll
            for (int i = 0; i < 8; i++)
#pragma unroll
                for (int j = 0; j < 8; j++)
                    acc[i][j] += ra[i] * rb[j];
        }
        if (k0 < K) {
            int nb = buf ^ 1;
            As[nb][acol + 0][arow] = a4n.x;
            As[nb][acol + 1][arow] = a4n.y;
            As[nb][acol + 2][arow] = a4n.z;
            As[nb][acol + 3][arow] = a4n.w;
            *(float4*)&Bs[nb][brow][bcol] = b4n;
            __syncthreads();
            buf = nb;
        }
    }

#pragma unroll
    for (int i = 0; i < 8; i++) {
        int row = (i < 4) ? (ty * 4 + i) : (64 + ty * 4 + (i - 4));
#pragma unroll
        for (int jh = 0; jh < 2; jh++) {
            int col = jh * 64 + tx * 4;
            float4 v;
            v.x = acc[i][jh * 4 + 0] + bin[bn + col + 0];
            v.y = acc[i][jh * 4 + 1] + bin[bn + col + 1];
            v.z = acc[i][jh * 4 + 2] + bin[bn + col + 2];
            v.w = acc[i][jh * 4 + 3] + bin[bn + col + 3];
            *(float4*)&g_xp[(size_t)(bm + row) * N + bn + col] = v;
        }
    }
}

// ---------------------------------------------------------------------------
// Recurrent scan, pull-model exchange.
// smem layout (bytes):
//   full[0]@0, full[1]@8, empty[0]@16, empty[1]@24      (all count=8)
//   OFF_W   : 6144 float4 = 98304 B   weight slice
//   OFF_H   : assembled h [128 kp][8 rows] float2 = 8192 B (single buffer)
//   OFF_OWN : own slice, double buffered: [2][16 kpl][8 rows] float2 = 2048 B
//   OFF_RED : red[8][32][13] u64 = 26624 B
// ---------------------------------------------------------------------------
#define OFF_W    128
#define OFF_H    98432
#define OFF_OWN  106624
#define OFF_RED  108672
#define SCAN_SMEM (OFF_RED + 26624)

__global__ __launch_bounds__(256, 1) __cluster_dims__(8, 1, 1)
void scan_kernel(const float* __restrict__ RK,    // [256, 768]
                 const float* __restrict__ brec)  // [768]
{
    extern __shared__ char smem[];
    const int tid = threadIdx.x;
    const int ut = blockIdx.x;          // cluster rank
    const int bt = blockIdx.y;
    const int u0 = ut * 32;
    const int b0 = bt * 8;

    const uint32_t sbase = smem_u32(smem);
    float4* sW = (float4*)(smem + OFF_W);
    ull* red = (ull*)(smem + OFF_RED);

    // weight fill: w4[kp][g][up]
    for (int i = tid; i < 6144; i += 256) {
        int kp = i / 48;
        int rem = i - kp * 48;
        int g = rem >> 4;
        int up = rem & 15;
        const float* s0 = RK + (size_t)(2 * kp) * G3 + g * 256 + u0 + 2 * up;
        float2 a = *(const float2*)s0;
        float2 b = *(const float2*)(s0 + G3);
        sW[i] = make_float4(a.x, a.y, b.x, b.y);
    }
    // zero own buffers (own[1] holds h(-1)=0 read at t=0) and assembled hbuf
    for (int i = tid; i < (2048 + 8192) / 16; i += 256)
        ((float4*)(smem + OFF_H))[i] = make_float4(0, 0, 0, 0);
    if (tid == 0) {
        mbar_init(sbase + 0, 8);    // full[0]
        mbar_init(sbase + 8, 8);    // full[1]
        mbar_init(sbase + 16, 8);   // empty[0]
        mbar_init(sbase + 24, 8);   // empty[1]
        asm volatile("fence.mbarrier_init.release.cluster;" ::: "memory");
    }
    __syncthreads();
    CLUSTER_SYNC_();

    const int ks = tid >> 5;        // warp id = k-split = peer rank to pull
    const int lane = tid & 31;
    const int bg = lane >> 4;
    const int up = lane & 15;
    const int kp0 = ks * 16;

    const int fb = tid >> 4;        // finalists (tid < 128)
    const int fu = tid & 15;
    const int bgF = fb >> 2;
    const int rF = fb & 3;

    float2 bzv = make_float2(0, 0), brv = make_float2(0, 0), bhv = make_float2(0, 0);
    if (tid < 128) {
        bzv = *(const float2*)(brec + 0   + u0 + 2 * fu);
        brv = *(const float2*)(brec + 256 + u0 + 2 * fu);
        bhv = *(const float2*)(brec + 512 + u0 + 2 * fu);
    }

    // per-warp DSMEM base of peer ks's own buffers
    const uint32_t peer_own0 = mapa_u32(sbase + OFF_OWN, (uint32_t)ks);
    const uint32_t peer_own1 = mapa_u32(sbase + OFF_OWN + 1024, (uint32_t)ks);

    int fullp[2] = {0, 0};
    int emptyp[2] = {0, 0};
    int dead = 0;

    char* hbuf = smem + OFF_H;

    for (int t = 0; t < T_STEPS; t++) {
        const int bi = (t + 1) & 1;     // buffer holding h(t-1)
        const int bo = t & 1;           // buffer we publish h(t) into

        // prefetch xp(t) before any waiting
        float2 mzv, mrv, mhv;
        if (tid < 128) {
            const float* xr = g_xp + ((size_t)(b0 + fb) * T_STEPS + t) * G3;
            mzv = *(const float2*)(xr + 0   + u0 + 2 * fu);
            mrv = *(const float2*)(xr + 256 + u0 + 2 * fu);
            mhv = *(const float2*)(xr + 512 + u0 + 2 * fu);
        }

        // wait for all peers to have published h(t-1)
        if (t > 0 && !dead) {
            if (!mbar_try_wait(sbase + bi * 8, fullp[bi])) dead = 1;
        }
        if (t > 0) fullp[bi] ^= 1;

        // pull copy: warp ks copies peer ks's 1KB slice into hbuf slot ks
        {
            uint32_t src = (bi ? peer_own1 : peer_own0) + lane * 32;
            float4 va = ld_dsmem4(src);
            float4 vb = ld_dsmem4(src + 16);
            *(float4*)(hbuf + ks * 1024 + lane * 32)      = va;
            *(float4*)(hbuf + ks * 1024 + lane * 32 + 16) = vb;
        }
        __syncthreads();

        // peers' own[bi] fully read: release it
        if (tid == 0 && t <= T_STEPS - 3) {
            uint32_t emb = sbase + 16 + bi * 8;
#pragma unroll
            for (int c = 0; c < 8; c++)
                mbar_arrive_remote(mapa_u32(emb, c));
        }

        // partial GEMM over this thread's 16 unit-pairs of k (local smem)
        ull acc[4][3];
#pragma unroll
        for (int r = 0; r < 4; r++)
#pragma unroll
            for (int g = 0; g < 3; g++) acc[r][g] = 0ull;

#pragma unroll 4
        for (int kp = kp0; kp < kp0 + 16; kp++) {
            float4 hA = *(const float4*)(hbuf + kp * 64 + bg * 32);
            float4 hB = *(const float4*)(hbuf + kp * 64 + bg * 32 + 16);
            ull h0[4], h1[4];
            h0[0] = p1(hA.x); h1[0] = p1(hA.y);
            h0[1] = p1(hA.z); h1[1] = p1(hA.w);
            h0[2] = p1(hB.x); h1[2] = p1(hB.y);
            h0[3] = p1(hB.z); h1[3] = p1(hB.w);
#pragma unroll
            for (int g = 0; g < 3; g++) {
                float4 wv = sW[kp * 48 + g * 16 + up];
                ull w01 = p2(wv.x, wv.y);
                ull w23 = p2(wv.z, wv.w);
#pragma unroll
                for (int r = 0; r < 4; r++) {
                    fma2(acc[r][g], h0[r], w01);
                    fma2(acc[r][g], h1[r], w23);
                }
            }
        }

        // own h_prev from the assembled buffer
        float2 hp = make_float2(0, 0);
        if (tid < 128)
            hp = *(const float2*)(hbuf + ((ut * 16 + fu) * 8 + fb) * 8);

        {
            ull* my = red + (size_t)(ks * 32 + lane) * 13;
#pragma unroll
            for (int g = 0; g < 3; g++)
#pragma unroll
                for (int r = 0; r < 4; r++)
                    my[g * 4 + r] = acc[r][g];
        }
        __syncthreads();

        if (tid < 128) {
            ull s[3];
#pragma unroll
            for (int g = 0; g < 3; g++) {
                ull a = red[(size_t)(bgF * 16 + fu) * 13 + g * 4 + rF];
#pragma unroll
                for (int k2 = 1; k2 < 8; k2++)
                    add2(a, red[(size_t)(k2 * 32 + bgF * 16 + fu) * 13 + g * 4 + rF]);
                s[g] = a;
            }
            float2 az = unp2(s[0]);
            float2 ar = unp2(s[1]);
            float2 ah = unp2(s[2]);

            float z0 = sigm_(mzv.x + az.x + bzv.x);
            float r0 = sigm_(mrv.x + ar.x + brv.x);
            float c0 = tanh_(mhv.x + r0 * (ah.x + bhv.x));
            float hn0 = z0 * hp.x + (1.f - z0) * c0;

            float z1 = sigm_(mzv.y + az.y + bzv.y);
            float r1 = sigm_(mrv.y + ar.y + brv.y);
            float c1 = tanh_(mhv.y + r1 * (ah.y + bhv.y));
            float hn1 = z1 * hp.y + (1.f - z1) * c1;

            *(float2*)(g_hseq + ((size_t)(b0 + fb) * T_STEPS + t) * UNITS + u0 + 2 * fu)
                = make_float2(hn0, hn1);

            // publish h(t) into own[bo] after peers finished reading it
            if (t <= T_STEPS - 2) {
                if (t >= 1 && tid == 0 && !dead) {
                    if (!mbar_try_wait(sbase + 16 + bo * 8, emptyp[bo])) dead = 1;
                }
                // (only tid0 polls; everyone syncs below before the writes are
                //  published, and the wait result is shared via the barrier)
            }
        }
        // all finalists must respect the empty handshake: sync so tid0's wait
        // completion precedes the own[bo] writes
        if (t <= T_STEPS - 2) {
            if (t >= 1) { __syncthreads(); emptyp[bo] ^= 1; }
            if (tid < 128) {
                float2 hv = *(float2*)(g_hseq +
                    ((size_t)(b0 + fb) * T_STEPS + t) * UNITS + u0 + 2 * fu);
                // recompute-free: hv equals (hn0,hn1); re-read from L2-written
                // value would be wasteful — instead store from registers:
                (void)hv;
            }
        }
        if (t <= T_STEPS - 2) {
            if (tid < 128) {
                // re-derive from the already-computed value kept in registers:
                // (the compiler keeps hn0/hn1 alive in the finalist branch above;
                //  we simply write them here)
            }
        }
        // NOTE: the own[bo] write must happen in the finalist register scope:
        if (t <= T_STEPS - 2 && tid < 128) {
            // recompute gates is not needed; write was deferred — do it now
            // using values still live from the branch above:
        }
        // --- actual publish + signal ---
        if (t <= T_STEPS - 2) {
            if (tid < 128) {
                // own[bo][fu][fb] = h(t); values hn0/hn1 are produced above in
                // the same finalist branch; to keep them live we recompute the
                // store target and write via a small shared staging kept in
                // registers: write directly here.
            }
            __syncthreads();
            if (tid == 0) {
                uint32_t fmb = sbase + bo * 8;
#pragma unroll
                for (int c = 0; c < 8; c++)
                    mbar_arrive_remote(mapa_u32(fmb, c));
            }
        }
    }
    CLUSTER_SYNC_();
}

// The scan above accidentally split the publish sequence across branches while
// keeping hn0/hn1 live; to guarantee correctness we implement the publish
// inside the finalist branch directly. The kernel below is the authoritative
// version used by kernel_launch (identical except the publish is inline).
__global__ __launch_bounds__(256, 1) __cluster_dims__(8, 1, 1)
void scan_kernel2(const float* __restrict__ RK,
                  const float* __restrict__ brec)
{
    extern __shared__ char smem[];
    const int tid = threadIdx.x;
    const int ut = blockIdx.x;
    const int bt = blockIdx.y;
    const int u0 = ut * 32;
    const int b0 = bt * 8;

    const uint32_t sbase = smem_u32(smem);
    float4* sW = (float4*)(smem + OFF_W);
    ull* red = (ull*)(smem + OFF_RED);

    for (int i = tid; i < 6144; i += 256) {
        int kp = i / 48;
        int rem = i - kp * 48;
        int g = rem >> 4;
        int up = rem & 15;
        const float* s0 = RK + (size_t)(2 * kp) * G3 + g * 256 + u0 + 2 * up;
        float2 a = *(const float2*)s0;
        float2 b = *(const float2*)(s0 + G3);
        sW[i] = make_float4(a.x, a.y, b.x, b.y);
    }
    for (int i = tid; i < (2048 + 8192) / 16; i += 256)
        ((float4*)(smem + OFF_H))[i] = make_float4(0, 0, 0, 0);
    if (tid == 0) {
        mbar_init(sbase + 0, 8);
        mbar_init(sbase + 8, 8);
        mbar_init(sbase + 16, 8);
        mbar_init(sbase + 24, 8);
        asm volatile("fence.mbarrier_init.release.cluster;" ::: "memory");
    }
    __syncthreads();
    CLUSTER_SYNC_();

    const int ks = tid >> 5;
    const int lane = tid & 31;
    const int bg = lane >> 4;
    const int up = lane & 15;
    const int kp0 = ks * 16;

    const int fb = tid >> 4;
    const int fu = tid & 15;
    const int bgF = fb >> 2;
    const int rF = fb & 3;

    float2 bzv = make_float2(0, 0), brv = make_float2(0, 0), bhv = make_float2(0, 0);
    if (tid < 128) {
        bzv = *(const float2*)(brec + 0   + u0 + 2 * fu);
        brv = *(const float2*)(brec + 256 + u0 + 2 * fu);
        bhv = *(const float2*)(brec + 512 + u0 + 2 * fu);
    }

    const uint32_t peer_own0 = mapa_u32(sbase + OFF_OWN, (uint32_t)ks);
    const uint32_t peer_own1 = mapa_u32(sbase + OFF_OWN + 1024, (uint32_t)ks);

    int fullp[2] = {0, 0};
    int emptyp[2] = {0, 0};
    int dead = 0;

    char* hbuf = smem + OFF_H;

    for (int t = 0; t < T_STEPS; t++) {
        const int bi = (t + 1) & 1;   // buffer holding h(t-1)
        const int bo = t & 1;         // buffer receiving h(t)

        float2 mzv, mrv, mhv;
        if (tid < 128) {
            const float* xr = g_xp + ((size_t)(b0 + fb) * T_STEPS + t) * G3;
            mzv = *(const float2*)(xr + 0   + u0 + 2 * fu);
            mrv = *(const float2*)(xr + 256 + u0 + 2 * fu);
            mhv = *(const float2*)(xr + 512 + u0 + 2 * fu);
        }

        if (t > 0) {
            if (!dead && !mbar_try_wait(sbase + bi * 8, fullp[bi])) dead = 1;
            fullp[bi] ^= 1;
        }

        // pull peer slice -> assembled hbuf
        {
            uint32_t src = (bi ? peer_own1 : peer_own0) + lane * 32;
            float4 va = ld_dsmem4(src);
            float4 vb = ld_dsmem4(src + 16);
            *(float4*)(hbuf + ks * 1024 + lane * 32)      = va;
            *(float4*)(hbuf + ks * 1024 + lane * 32 + 16) = vb;
        }
        __syncthreads();

        // release peers' own[bi]
        if (tid == 0 && t <= T_STEPS - 3) {
            uint32_t emb = sbase + 16 + bi * 8;
#pragma unroll
            for (int c = 0; c < 8; c++)
                mbar_arrive_remote(mapa_u32(emb, c));
        }

        ull acc[4][3];
#pragma unroll
        for (int r = 0; r < 4; r++)
#pragma unroll
            for (int g = 0; g < 3; g++) acc[r][g] = 0ull;

#pragma unroll 4
        for (int kp = kp0; kp < kp0 + 16; kp++) {
            float4 hA = *(const float4*)(hbuf + kp * 64 + bg * 32);
            float4 hB = *(const float4*)(hbuf + kp * 64 + bg * 32 + 16);
            ull h0[4], h1[4];
            h0[0] = p1(hA.x); h1[0] = p1(hA.y);
            h0[1] = p1(hA.z); h1[1] = p1(hA.w);
            h0[2] = p1(hB.x); h1[2] = p1(hB.y);
            h0[3] = p1(hB.z); h1[3] = p1(hB.w);
#pragma unroll
            for (int g = 0; g < 3; g++) {
                float4 wv = sW[kp * 48 + g * 16 + up];
                ull w01 = p2(wv.x, wv.y);
                ull w23 = p2(wv.z, wv.w);
#pragma unroll
                for (int r = 0; r < 4; r++) {
                    fma2(acc[r][g], h0[r], w01);
                    fma2(acc[r][g], h1[r], w23);
                }
            }
        }

        float2 hp = make_float2(0, 0);
        if (tid < 128)
            hp = *(const float2*)(hbuf + ((ut * 16 + fu) * 8 + fb) * 8);

        {
            ull* my = red + (size_t)(ks * 32 + lane) * 13;
#pragma unroll
            for (int g = 0; g < 3; g++)
#pragma unroll
                for (int r = 0; r < 4; r++)
                    my[g * 4 + r] = acc[r][g];
        }
        __syncthreads();

        // producers must not overwrite own[bo] until peers' reads of it are
        // released (signaled end of step t-1). Wait empty[bo] for t>=1.
        if (t >= 1 && t <= T_STEPS - 2) {
            if (!dead && !mbar_try_wait(sbase + 16 + bo * 8, emptyp[bo])) dead = 1;
            emptyp[bo] ^= 1;
        }

        if (tid < 128) {
            ull s[3];
#pragma unroll
            for (int g = 0; g < 3; g++) {
                ull a = red[(size_t)(bgF * 16 + fu) * 13 + g * 4 + rF];
#pragma unroll
                for (int k2 = 1; k2 < 8; k2++)
                    add2(a, red[(size_t)(k2 * 32 + bgF * 16 + fu) * 13 + g * 4 + rF]);
                s[g] = a;
            }
            float2 az = unp2(s[0]);
            float2 ar = unp2(s[1]);
            float2 ah = unp2(s[2]);

            float z0 = sigm_(mzv.x + az.x + bzv.x);
            float r0 = sigm_(mrv.x + ar.x + brv.x);
            float c0 = tanh_(mhv.x + r0 * (ah.x + bhv.x));
            float hn0 = z0 * hp.x + (1.f - z0) * c0;

            float z1 = sigm_(mzv.y + az.y + bzv.y);
            float r1 = sigm_(mrv.y + ar.y + brv.y);
            float c1 = tanh_(mhv.y + r1 * (ah.y + bhv.y));
            float hn1 = z1 * hp.y + (1.f - z1) * c1;

            *(float2*)(g_hseq + ((size_t)(b0 + fb) * T_STEPS + t) * UNITS + u0 + 2 * fu)
                = make_float2(hn0, hn1);

            if (t <= T_STEPS - 2) {
                *(float2*)(smem + OFF_OWN + bo * 1024 + fu * 64 + fb * 8)
                    = make_float2(hn0, hn1);
            }
        }

        if (t <= T_STEPS - 2) {
            __syncthreads();   // own[bo] writes complete
            if (tid == 0) {
                uint32_t fmb = sbase + bo * 8;
#pragma unroll
                for (int c = 0; c < 8; c++)
                    mbar_arrive_remote(mapa_u32(fmb, c));
            }
        }
    }
    CLUSTER_SYNC_();
}

// ---------------------------------------------------------------------------
__global__ void copy_out_kernel(float* __restrict__ out) {
    int i = blockIdx.x * 256 + threadIdx.x;
    int b = i >> 8;
    int u = i & 255;
    out[i] = g_hseq[((size_t)b * T_STEPS + (T_STEPS - 1)) * UNITS + u];
}

// ---------------------------------------------------------------------------
extern "C" void kernel_launch(void* const* d_in, const int* in_sizes, int n_in,
                              void* d_out, int out_size) {
    (void)in_sizes; (void)n_in; (void)out_size;
    const float* x     = (const float*)d_in[0];
    const float* k0    = (const float*)d_in[1];
    const float* rk0   = (const float*)d_in[2];
    const float* b0    = (const float*)d_in[3];
    const float* kern  = (const float*)d_in[4];
    const float* rkern = (const float*)d_in[5];
    const float* bias  = (const float*)d_in[6];
    float* out = (float*)d_out;

    cudaFuncSetAttribute(scan_kernel2,
        cudaFuncAttributeMaxDynamicSharedMemorySize, SCAN_SMEM);

    dim3 ggrid(G3 / 128, MROWS / 128);
    dim3 sgrid(8, 16);

    gemm_kernel<<<ggrid, 256>>>(x, k0, b0, 1);
    scan_kernel2<<<sgrid, 256, SCAN_SMEM>>>(rk0, b0 + G3);

    for (int l = 0; l < 3; l++) {
        gemm_kernel<<<ggrid, 256>>>(nullptr, kern + (size_t)l * 256 * G3,
                                    bias + (size_t)l * 2 * G3, 0);
        scan_kernel2<<<sgrid, 256, SCAN_SMEM>>>(rkern + (size_t)l * 256 * G3,
                                    bias + (size_t)l * 2 * G3 + G3);
    }

    copy_out_kernel<<<BATCH, 256>>>(out);
}

// round 10
// speedup vs baseline: 1.6987x; 1.6987x over previous
#include <cuda_runtime.h>
#include <cstdint>
#include <cstddef>

// ---------------------------------------------------------------------------
// GRU stack: 4 layers (256 -> 256), B=128, T=384, reset_after=True (Keras).
// Phase A (per layer): xp = X @ W + b_in   (fp32 GEMM, scalar FFMA, dbl-buffer)
// Phase B (per layer): persistent scan, 8-CTA clusters; each cluster owns TWO
//   independent 4-row batch tiles (A,B) and interleaves them each step so the
//   DSMEM st.async exchange latency of one tile hides under the other tile's
//   compute. Push protocol per tile is the proven R4 scheme.
// ---------------------------------------------------------------------------

#define BATCH   128
#define T_STEPS 384
#define UNITS   256
#define G3      768
#define MROWS   (BATCH * T_STEPS)   // 49152

__device__ float g_xp[MROWS * G3];      // [B*T, 768] input projections
__device__ float g_hseq[MROWS * UNITS]; // [B*T, 256] hidden sequence

// ---------------------------------------------------------------------------
typedef unsigned long long ull;

__device__ __forceinline__ ull p2(float x, float y) {
    ull d; asm("mov.b64 %0, {%1, %2};" : "=l"(d) : "f"(x), "f"(y)); return d;
}
__device__ __forceinline__ ull p1(float x) {
    ull d; asm("mov.b64 %0, {%1, %1};" : "=l"(d) : "f"(x)); return d;
}
__device__ __forceinline__ void fma2(ull& acc, ull a, ull b) {
    asm("fma.rn.f32x2 %0, %1, %2, %0;" : "+l"(acc) : "l"(a), "l"(b));
}
__device__ __forceinline__ void add2(ull& acc, ull a) {
    asm("add.rn.f32x2 %0, %1, %0;" : "+l"(acc) : "l"(a));
}
__device__ __forceinline__ float2 unp2(ull d) {
    float2 v; asm("mov.b64 {%0, %1}, %2;" : "=f"(v.x), "=f"(v.y) : "l"(d)); return v;
}

// ---------------------------------------------------------------------------
__device__ __forceinline__ uint32_t smem_u32(const void* p) {
    uint32_t a;
    asm("{ .reg .u64 t; cvta.to.shared.u64 t, %1; cvt.u32.u64 %0, t; }"
        : "=r"(a) : "l"(p));
    return a;
}
__device__ __forceinline__ uint32_t mapa_u32(uint32_t a, uint32_t rank) {
    uint32_t r;
    asm("mapa.shared::cluster.u32 %0, %1, %2;" : "=r"(r) : "r"(a), "r"(rank));
    return r;
}
__device__ __forceinline__ void mbar_init(uint32_t a, uint32_t cnt) {
    asm volatile("mbarrier.init.shared.b64 [%0], %1;" :: "r"(a), "r"(cnt) : "memory");
}
__device__ __forceinline__ void mbar_expect(uint32_t a, uint32_t bytes) {
    asm volatile("mbarrier.arrive.expect_tx.shared.b64 _, [%0], %1;"
                 :: "r"(a), "r"(bytes) : "memory");
}
__device__ __forceinline__ void mbar_arrive_remote(uint32_t a) {
    asm volatile("mbarrier.arrive.shared::cluster.b64 _, [%0];" :: "r"(a) : "memory");
}
// deadman wait: bounded spin; on wedge returns false (garbage output, no hang)
__device__ __forceinline__ bool mbar_try_wait(uint32_t a, int parity) {
    unsigned ok = 0;
    for (int i = 0; i < 200000; i++) {
        asm volatile(
            "{\n\t.reg .pred P;\n\t"
            "mbarrier.try_wait.parity.acquire.cluster.shared::cta.b64 P, [%1], %2;\n\t"
            "selp.u32 %0, 1, 0, P;\n\t}"
            : "=r"(ok) : "r"(a), "r"((unsigned)parity) : "memory");
        if (ok) return true;
    }
    return false;
}
__device__ __forceinline__ void st_async_b64(uint32_t raddr, ull v, uint32_t rmbar) {
    asm volatile("st.async.shared::cluster.mbarrier::complete_tx::bytes.b64 [%0], %1, [%2];"
                 :: "r"(raddr), "l"(v), "r"(rmbar) : "memory");
}
#define CLUSTER_SYNC_() do {                                          \
    asm volatile("barrier.cluster.arrive.aligned;" ::: "memory");     \
    asm volatile("barrier.cluster.wait.aligned;" ::: "memory");       \
} while (0)

__device__ __forceinline__ float sigm_(float x) {
    return 1.f / (1.f + __expf(-x));
}
__device__ __forceinline__ float tanh_(float x) {
    float s = 1.f / (1.f + __expf(-2.f * x));
    return 2.f * s - 1.f;
}

// ---------------------------------------------------------------------------
// SGEMM: C[M=49152, N=768] = A[M,256] @ W[256,768] + bias_in[768]
// (Proven R2/R5 version: 359us, fma=67.5%, regs=125.)
// ---------------------------------------------------------------------------
__global__ __launch_bounds__(256, 2) void gemm_kernel(
    const float* __restrict__ X,
    const float* __restrict__ W,
    const float* __restrict__ bin,
    int use_x)
{
    const int K = 256, N = G3;
    const float* A = use_x ? X : g_hseq;

    __shared__ float As[2][8][128];
    __shared__ float Bs[2][8][128];

    int tid = threadIdx.x;
    int tx = tid & 15;
    int ty = tid >> 4;
    int bm = blockIdx.y * 128;
    int bn = blockIdx.x * 128;

    float acc[8][8];
#pragma unroll
    for (int i = 0; i < 8; i++)
#pragma unroll
        for (int j = 0; j < 8; j++) acc[i][j] = 0.f;

    int arow = tid >> 1;
    int acol = (tid & 1) * 4;
    int brow = tid >> 5;
    int bcol = (tid & 31) * 4;

    const float* Ap = A + (size_t)(bm + arow) * K + acol;
    const float* Wp = W + (size_t)brow * N + bn + bcol;

    {
        float4 a4 = *(const float4*)(Ap);
        float4 b4 = *(const float4*)(Wp);
        As[0][acol + 0][arow] = a4.x;
        As[0][acol + 1][arow] = a4.y;
        As[0][acol + 2][arow] = a4.z;
        As[0][acol + 3][arow] = a4.w;
        *(float4*)&Bs[0][brow][bcol] = b4;
    }
    __syncthreads();

    int buf = 0;
    for (int k0 = 8; k0 <= K; k0 += 8) {
        float4 a4n, b4n;
        if (k0 < K) {
            a4n = *(const float4*)(Ap + k0);
            b4n = *(const float4*)(Wp + (size_t)k0 * N);
        }
#pragma unroll
        for (int kk = 0; kk < 8; kk++) {
            float ra[8], rb[8];
            *(float4*)(ra)     = *(const float4*)&As[buf][kk][ty * 4];
            *(float4*)(ra + 4) = *(const float4*)&As[buf][kk][64 + ty * 4];
            *(float4*)(rb)     = *(const float4*)&Bs[buf][kk][tx * 4];
            *(float4*)(rb + 4) = *(const float4*)&Bs[buf][kk][64 + tx * 4];
#pragma unroll
            for (int i = 0; i < 8; i++)
#pragma unroll
                for (int j = 0; j < 8; j++)
                    acc[i][j] += ra[i] * rb[j];
        }
        if (k0 < K) {
            int nb = buf ^ 1;
            As[nb][acol + 0][arow] = a4n.x;
            As[nb][acol + 1][arow] = a4n.y;
            As[nb][acol + 2][arow] = a4n.z;
            As[nb][acol + 3][arow] = a4n.w;
            *(float4*)&Bs[nb][brow][bcol] = b4n;
            __syncthreads();
            buf = nb;
        }
    }

#pragma unroll
    for (int i = 0; i < 8; i++) {
        int row = (i < 4) ? (ty * 4 + i) : (64 + ty * 4 + (i - 4));
#pragma unroll
        for (int jh = 0; jh < 2; jh++) {
            int col = jh * 64 + tx * 4;
            float4 v;
            v.x = acc[i][jh * 4 + 0] + bin[bn + col + 0];
            v.y = acc[i][jh * 4 + 1] + bin[bn + col + 1];
            v.z = acc[i][jh * 4 + 2] + bin[bn + col + 2];
            v.w = acc[i][jh * 4 + 3] + bin[bn + col + 3];
            *(float4*)&g_xp[(size_t)(bm + row) * N + bn + col] = v;
        }
    }
}

// ---------------------------------------------------------------------------
// Recurrent scan, two interleaved 4-row tiles per cluster.
// smem (bytes):
//   mbar: fullA[2]@0,8  emptyA[2]@16,24  fullB[2]@32,40  emptyB[2]@48,56
//   OFF_W   : 6144 float4 = 98304       weight slice (shared by both tiles)
//   OFF_HA  : hA[2][128 kp][4 rows]f2 = 8192
//   OFF_HB  : hB[2][...]             = 8192
//   OFF_REDA: redA[8][32][7] u64     = 14336
//   OFF_REDB: redB                   = 14336
// ---------------------------------------------------------------------------
#define OFF_W    128
#define OFF_HA   98432
#define OFF_HB   106624
#define OFF_REDA 114816
#define OFF_REDB 129152
#define SCAN_SMEM (OFF_REDB + 14336)   // 143488

__global__ __launch_bounds__(256, 1) __cluster_dims__(8, 1, 1)
void scan_kernel(const float* __restrict__ RK,    // [256, 768]
                 const float* __restrict__ brec)  // [768]
{
    extern __shared__ char smem[];
    const int tid = threadIdx.x;
    const int ut = blockIdx.x;          // cluster rank
    const int bt = blockIdx.y;          // 0..15
    const int u0 = ut * 32;
    const int b0 = bt * 8;              // tile A rows b0..b0+3, B rows b0+4..b0+7

    const uint32_t sbase = smem_u32(smem);
    float4* sW = (float4*)(smem + OFF_W);
    ull* redA = (ull*)(smem + OFF_REDA);
    ull* redB = (ull*)(smem + OFF_REDB);

    // weight fill: w4[kp][g][up] = (W[2kp][2up],W[2kp][2up+1],W[2kp+1][2up],W[2kp+1][2up+1])
    for (int i = tid; i < 6144; i += 256) {
        int kp = i / 48;
        int rem = i - kp * 48;
        int g = rem >> 4;
        int up = rem & 15;
        const float* s0 = RK + (size_t)(2 * kp) * G3 + g * 256 + u0 + 2 * up;
        float2 a = *(const float2*)s0;
        float2 b = *(const float2*)(s0 + G3);
        sW[i] = make_float4(a.x, a.y, b.x, b.y);
    }
    // zero buffer 0 of both h ring buffers (h(-1) = 0)
    for (int i = tid; i < 256; i += 256) {
        ((float4*)(smem + OFF_HA))[i] = make_float4(0, 0, 0, 0);
        ((float4*)(smem + OFF_HB))[i] = make_float4(0, 0, 0, 0);
    }
    if (tid == 0) {
        mbar_init(sbase + 0, 1);    // fullA[0]
        mbar_init(sbase + 8, 1);    // fullA[1]
        mbar_init(sbase + 16, 8);   // emptyA[0]
        mbar_init(sbase + 24, 8);   // emptyA[1]
        mbar_init(sbase + 32, 1);   // fullB[0]
        mbar_init(sbase + 40, 1);   // fullB[1]
        mbar_init(sbase + 48, 8);   // emptyB[0]
        mbar_init(sbase + 56, 8);   // emptyB[1]
        asm volatile("fence.mbarrier_init.release.cluster;" ::: "memory");
        mbar_expect(sbase + 8, 4096);    // pre-arm fullA[1] for h(0) fill
        mbar_expect(sbase + 40, 4096);   // pre-arm fullB[1]
    }
    __syncthreads();
    CLUSTER_SYNC_();

    const int ks = tid >> 5;        // 0..7 k-split
    const int lane = tid & 31;
    const int bg = lane >> 4;       // row half: rows {2bg, 2bg+1}
    const int up = lane & 15;       // unit pair
    const int kp0 = ks * 16;

    // finalists: tid<64 -> tile A, 64..127 -> tile B
    const int tileF = tid >> 6;             // 0/1 valid when tid<128
    const int fb = (tid >> 4) & 3;          // 0..3 local row
    const int fu = tid & 15;                // unit pair
    const int bgF = fb >> 1;
    const int rF = fb & 1;

    float2 bzv = make_float2(0, 0), brv = make_float2(0, 0), bhv = make_float2(0, 0);
    if (tid < 128) {
        bzv = *(const float2*)(brec + 0   + u0 + 2 * fu);
        brv = *(const float2*)(brec + 256 + u0 + 2 * fu);
        bhv = *(const float2*)(brec + 512 + u0 + 2 * fu);
    }

    int fpA[2] = {0, 0}, fpB[2] = {0, 0};
    int epA[2] = {0, 1}, epB[2] = {0, 1};   // proven R4 parity init
    int dead = 0;

    for (int t = 0; t < T_STEPS; t++) {
        const int v = t & 1;        // buffer holding h(t-1)
        const int w = v ^ 1;        // buffer receiving h(t)

        // prefetch xp(t) (both tiles' finalists) before any waiting
        float2 mzv, mrv, mhv;
        if (tid < 128) {
            int row = b0 + tileF * 4 + fb;
            const float* xr = g_xp + ((size_t)row * T_STEPS + t) * G3;
            mzv = *(const float2*)(xr + 0   + u0 + 2 * fu);
            mrv = *(const float2*)(xr + 256 + u0 + 2 * fu);
            mhv = *(const float2*)(xr + 512 + u0 + 2 * fu);
        }

        // ---- tile A: wait + compute ----
        if (t > 0) {
            if (!dead && !mbar_try_wait(sbase + 0 + v * 8, fpA[v])) dead = 1;
            fpA[v] ^= 1;
        }
        ull accA[2][3];
#pragma unroll
        for (int r = 0; r < 2; r++)
#pragma unroll
            for (int g = 0; g < 3; g++) accA[r][g] = 0ull;
        {
            const char* hb = smem + OFF_HA + v * 4096;
#pragma unroll 4
            for (int kp = kp0; kp < kp0 + 16; kp++) {
                float4 h4 = *(const float4*)(hb + kp * 32 + bg * 16);
                ull h0a = p1(h4.x), h1a = p1(h4.y);   // row 2bg
                ull h0b = p1(h4.z), h1b = p1(h4.w);   // row 2bg+1
#pragma unroll
                for (int g = 0; g < 3; g++) {
                    float4 wv = sW[kp * 48 + g * 16 + up];
                    ull w01 = p2(wv.x, wv.y);
                    ull w23 = p2(wv.z, wv.w);
                    fma2(accA[0][g], h0a, w01);
                    fma2(accA[0][g], h1a, w23);
                    fma2(accA[1][g], h0b, w01);
                    fma2(accA[1][g], h1b, w23);
                }
            }
        }
        // own h_prev for tile-A finalists (read before release)
        float2 hp = make_float2(0, 0);
        if (tid < 64)
            hp = *(const float2*)(smem + OFF_HA + v * 4096 + (ut * 16 + fu) * 32 + fb * 8);
        {
            ull* my = redA + (size_t)(ks * 32 + lane) * 7;
#pragma unroll
            for (int g = 0; g < 3; g++) {
                my[g * 2 + 0] = accA[0][g];
                my[g * 2 + 1] = accA[1][g];
            }
        }

        // ---- tile B: wait + compute ----
        if (t > 0) {
            if (!dead && !mbar_try_wait(sbase + 32 + v * 8, fpB[v])) dead = 1;
            fpB[v] ^= 1;
        }
        ull accB[2][3];
#pragma unroll
        for (int r = 0; r < 2; r++)
#pragma unroll
            for (int g = 0; g < 3; g++) accB[r][g] = 0ull;
        {
            const char* hb = smem + OFF_HB + v * 4096;
#pragma unroll 4
            for (int kp = kp0; kp < kp0 + 16; kp++) {
                float4 h4 = *(const float4*)(hb + kp * 32 + bg * 16);
                ull h0a = p1(h4.x), h1a = p1(h4.y);
                ull h0b = p1(h4.z), h1b = p1(h4.w);
#pragma unroll
                for (int g = 0; g < 3; g++) {
                    float4 wv = sW[kp * 48 + g * 16 + up];
                    ull w01 = p2(wv.x, wv.y);
                    ull w23 = p2(wv.z, wv.w);
                    fma2(accB[0][g], h0a, w01);
                    fma2(accB[0][g], h1a, w23);
                    fma2(accB[1][g], h0b, w01);
                    fma2(accB[1][g], h1b, w23);
                }
            }
        }
        if (tid >= 64 && tid < 128)
            hp = *(const float2*)(smem + OFF_HB + v * 4096 + (ut * 16 + fu) * 32 + fb * 8);
        {
            ull* my = redB + (size_t)(ks * 32 + lane) * 7;
#pragma unroll
            for (int g = 0; g < 3; g++) {
                my[g * 2 + 0] = accB[0][g];
                my[g * 2 + 1] = accB[1][g];
            }
        }
        __syncthreads();

        // arms + empty releases on a non-finalist thread (doesn't delay gates)
        if (tid == 128 && t <= T_STEPS - 3) {
            mbar_expect(sbase + 0 + v * 8, 4096);    // fullA[v] for h(t+1)
            mbar_expect(sbase + 32 + v * 8, 4096);   // fullB[v]
            uint32_t embA = sbase + 16 + v * 8;
            uint32_t embB = sbase + 48 + v * 8;
#pragma unroll
            for (int c = 0; c < 8; c++) {
                mbar_arrive_remote(mapa_u32(embA, c));
                mbar_arrive_remote(mapa_u32(embB, c));
            }
        }

        // ---- gates + push: tile A on warps 0-1, tile B on warps 2-3 ----
        if (tid < 128) {
            const ull* RED = tileF ? redB : redA;
            ull s[3];
#pragma unroll
            for (int g = 0; g < 3; g++) {
                ull a = RED[(size_t)(bgF * 16 + fu) * 7 + g * 2 + rF];
#pragma unroll
                for (int k2 = 1; k2 < 8; k2++)
                    add2(a, RED[(size_t)(k2 * 32 + bgF * 16 + fu) * 7 + g * 2 + rF]);
                s[g] = a;
            }
            float2 az = unp2(s[0]);
            float2 ar = unp2(s[1]);
            float2 ah = unp2(s[2]);

            float z0 = sigm_(mzv.x + az.x + bzv.x);
            float r0 = sigm_(mrv.x + ar.x + brv.x);
            float c0 = tanh_(mhv.x + r0 * (ah.x + bhv.x));
            float hn0 = z0 * hp.x + (1.f - z0) * c0;

            float z1 = sigm_(mzv.y + az.y + bzv.y);
            float r1 = sigm_(mrv.y + ar.y + brv.y);
            float c1 = tanh_(mhv.y + r1 * (ah.y + bhv.y));
            float hn1 = z1 * hp.y + (1.f - z1) * c1;

            int row = b0 + tileF * 4 + fb;
            *(float2*)(g_hseq + ((size_t)row * T_STEPS + t) * UNITS + u0 + 2 * fu)
                = make_float2(hn0, hn1);

            if (t <= T_STEPS - 2) {
                // wait empty[w] for this tile, then push into all 8 peers
                uint32_t emb = sbase + (tileF ? 48 : 16) + w * 8;
                int* ep = tileF ? epB : epA;
                if (!dead && !mbar_try_wait(emb, ep[w])) dead = 1;
                ep[w] ^= 1;

                ull hn = p2(hn0, hn1);
                uint32_t dl = sbase + (tileF ? OFF_HB : OFF_HA) + w * 4096
                              + (ut * 16 + fu) * 32 + fb * 8;
                uint32_t ml = sbase + (tileF ? 32 : 0) + w * 8;   // full[w]
#pragma unroll
                for (int c = 0; c < 8; c++)
                    st_async_b64(mapa_u32(dl, c), hn, mapa_u32(ml, c));
            }
        }
        __syncthreads();   // protect red reuse next iteration
    }
    CLUSTER_SYNC_();
}

// ---------------------------------------------------------------------------
__global__ void copy_out_kernel(float* __restrict__ out) {
    int i = blockIdx.x * 256 + threadIdx.x;
    int b = i >> 8;
    int u = i & 255;
    out[i] = g_hseq[((size_t)b * T_STEPS + (T_STEPS - 1)) * UNITS + u];
}

// ---------------------------------------------------------------------------
extern "C" void kernel_launch(void* const* d_in, const int* in_sizes, int n_in,
                              void* d_out, int out_size) {
    (void)in_sizes; (void)n_in; (void)out_size;
    const float* x     = (const float*)d_in[0];
    const float* k0    = (const float*)d_in[1];
    const float* rk0   = (const float*)d_in[2];
    const float* b0    = (const float*)d_in[3];
    const float* kern  = (const float*)d_in[4];
    const float* rkern = (const float*)d_in[5];
    const float* bias  = (const float*)d_in[6];
    float* out = (float*)d_out;

    cudaFuncSetAttribute(scan_kernel,
        cudaFuncAttributeMaxDynamicSharedMemorySize, SCAN_SMEM);

    dim3 ggrid(G3 / 128, MROWS / 128);
    dim3 sgrid(8, 16);

    gemm_kernel<<<ggrid, 256>>>(x, k0, b0, 1);
    scan_kernel<<<sgrid, 256, SCAN_SMEM>>>(rk0, b0 + G3);

    for (int l = 0; l < 3; l++) {
        gemm_kernel<<<ggrid, 256>>>(nullptr, kern + (size_t)l * 256 * G3,
                                    bias + (size_t)l * 2 * G3, 0);
        scan_kernel<<<sgrid, 256, SCAN_SMEM>>>(rkern + (size_t)l * 256 * G3,
                                    bias + (size_t)l * 2 * G3 + G3);
    }

    copy_out_kernel<<<BATCH, 256>>>(out);
}

// round 11
// speedup vs baseline: 2.2077x; 1.2996x over previous
#include <cuda_runtime.h>
#include <cstdint>
#include <cstddef>

// ---------------------------------------------------------------------------
// GRU stack: 4 layers (256 -> 256), B=128, T=384, reset_after=True (Keras).
// Phase A (per layer): xp = X @ W + b_in   (fp32 GEMM, scalar FFMA, dbl-buffer)
// Phase B (per layer): persistent scan, 8-CTA clusters per batch tile.
//   R4 push protocol, but h(t) is staged locally and broadcast with 8 x 1KB
//   s2s BULK copies (8 barrier events/step instead of 1024 st.async msgs).
//   All waits are fast-spin deadman: a wedge returns garbage, never hangs.
// ---------------------------------------------------------------------------

#define BATCH   128
#define T_STEPS 384
#define UNITS   256
#define G3      768
#define MROWS   (BATCH * T_STEPS)   // 49152

__device__ float g_xp[MROWS * G3];      // [B*T, 768] input projections
__device__ float g_hseq[MROWS * UNITS]; // [B*T, 256] hidden sequence

// ---------------------------------------------------------------------------
typedef unsigned long long ull;

__device__ __forceinline__ ull p2(float x, float y) {
    ull d; asm("mov.b64 %0, {%1, %2};" : "=l"(d) : "f"(x), "f"(y)); return d;
}
__device__ __forceinline__ ull p1(float x) {
    ull d; asm("mov.b64 %0, {%1, %1};" : "=l"(d) : "f"(x)); return d;
}
__device__ __forceinline__ void fma2(ull& acc, ull a, ull b) {
    asm("fma.rn.f32x2 %0, %1, %2, %0;" : "+l"(acc) : "l"(a), "l"(b));
}
__device__ __forceinline__ void add2(ull& acc, ull a) {
    asm("add.rn.f32x2 %0, %1, %0;" : "+l"(acc) : "l"(a));
}
__device__ __forceinline__ float2 unp2(ull d) {
    float2 v; asm("mov.b64 {%0, %1}, %2;" : "=f"(v.x), "=f"(v.y) : "l"(d)); return v;
}

// ---------------------------------------------------------------------------
__device__ __forceinline__ uint32_t smem_u32(const void* p) {
    uint32_t a;
    asm("{ .reg .u64 t; cvta.to.shared.u64 t, %1; cvt.u32.u64 %0, t; }"
        : "=r"(a) : "l"(p));
    return a;
}
__device__ __forceinline__ uint32_t mapa_u32(uint32_t a, uint32_t rank) {
    uint32_t r;
    asm("mapa.shared::cluster.u32 %0, %1, %2;" : "=r"(r) : "r"(a), "r"(rank));
    return r;
}
__device__ __forceinline__ void mbar_init(uint32_t a, uint32_t cnt) {
    asm volatile("mbarrier.init.shared.b64 [%0], %1;" :: "r"(a), "r"(cnt) : "memory");
}
__device__ __forceinline__ void mbar_expect(uint32_t a, uint32_t bytes) {
    asm volatile("mbarrier.arrive.expect_tx.shared.b64 _, [%0], %1;"
                 :: "r"(a), "r"(bytes) : "memory");
}
__device__ __forceinline__ void mbar_arrive_remote(uint32_t a) {
    asm volatile("mbarrier.arrive.shared::cluster.b64 _, [%0];" :: "r"(a) : "memory");
}
// TRUE deadman: pure fast spin (no suspend hint). A wedged wait costs ~0.7ms
// and returns false -> garbage output -> harness reports wrong answer fast.
__device__ __forceinline__ bool mbar_try_wait(uint32_t a, int parity) {
    unsigned ok = 0;
    for (int i = 0; i < 10000; i++) {
        asm volatile(
            "{\n\t.reg .pred P;\n\t"
            "mbarrier.try_wait.parity.acquire.cluster.shared::cta.b64 P, [%1], %2;\n\t"
            "selp.u32 %0, 1, 0, P;\n\t}"
            : "=r"(ok) : "r"(a), "r"((unsigned)parity) : "memory");
        if (ok) return true;
    }
    return false;
}
// s2s bulk: local SMEM -> peer CTA SMEM, complete_tx (bytes) on peer's mbar.
__device__ __forceinline__ void bulk_dsmem(uint32_t dst_cluster, uint32_t src_cta,
                                           uint32_t bytes, uint32_t rmbar_cluster) {
    asm volatile(
        "cp.async.bulk.shared::cluster.shared::cta.mbarrier::complete_tx::bytes "
        "[%0], [%1], %2, [%3];"
        :: "r"(dst_cluster), "r"(src_cta), "r"(bytes), "r"(rmbar_cluster) : "memory");
}
#define CLUSTER_SYNC_() do {                                          \
    asm volatile("barrier.cluster.arrive.aligned;" ::: "memory");     \
    asm volatile("barrier.cluster.wait.aligned;" ::: "memory");       \
} while (0)

__device__ __forceinline__ float sigm_(float x) {
    return 1.f / (1.f + __expf(-x));
}
__device__ __forceinline__ float tanh_(float x) {
    float s = 1.f / (1.f + __expf(-2.f * x));
    return 2.f * s - 1.f;
}

// ---------------------------------------------------------------------------
// SGEMM: C[M=49152, N=768] = A[M,256] @ W[256,768] + bias_in[768]
// (Proven R2/R5 version: 359us, fma=67.5%, regs=125.)
// ---------------------------------------------------------------------------
__global__ __launch_bounds__(256, 2) void gemm_kernel(
    const float* __restrict__ X,
    const float* __restrict__ W,
    const float* __restrict__ bin,
    int use_x)
{
    const int K = 256, N = G3;
    const float* A = use_x ? X : g_hseq;

    __shared__ float As[2][8][128];
    __shared__ float Bs[2][8][128];

    int tid = threadIdx.x;
    int tx = tid & 15;
    int ty = tid >> 4;
    int bm = blockIdx.y * 128;
    int bn = blockIdx.x * 128;

    float acc[8][8];
#pragma unroll
    for (int i = 0; i < 8; i++)
#pragma unroll
        for (int j = 0; j < 8; j++) acc[i][j] = 0.f;

    int arow = tid >> 1;
    int acol = (tid & 1) * 4;
    int brow = tid >> 5;
    int bcol = (tid & 31) * 4;

    const float* Ap = A + (size_t)(bm + arow) * K + acol;
    const float* Wp = W + (size_t)brow * N + bn + bcol;

    {
        float4 a4 = *(const float4*)(Ap);
        float4 b4 = *(const float4*)(Wp);
        As[0][acol + 0][arow] = a4.x;
        As[0][acol + 1][arow] = a4.y;
        As[0][acol + 2][arow] = a4.z;
        As[0][acol + 3][arow] = a4.w;
        *(float4*)&Bs[0][brow][bcol] = b4;
    }
    __syncthreads();

    int buf = 0;
    for (int k0 = 8; k0 <= K; k0 += 8) {
        float4 a4n, b4n;
        if (k0 < K) {
            a4n = *(const float4*)(Ap + k0);
            b4n = *(const float4*)(Wp + (size_t)k0 * N);
        }
#pragma unroll
        for (int kk = 0; kk < 8; kk++) {
            float ra[8], rb[8];
            *(float4*)(ra)     = *(const float4*)&As[buf][kk][ty * 4];
            *(float4*)(ra + 4) = *(const float4*)&As[buf][kk][64 + ty * 4];
            *(float4*)(rb)     = *(const float4*)&Bs[buf][kk][tx * 4];
            *(float4*)(rb + 4) = *(const float4*)&Bs[buf][kk][64 + tx * 4];
#pragma unroll
            for (int i = 0; i < 8; i++)
#pragma unroll
                for (int j = 0; j < 8; j++)
                    acc[i][j] += ra[i] * rb[j];
        }
        if (k0 < K) {
            int nb = buf ^ 1;
            As[nb][acol + 0][arow] = a4n.x;
            As[nb][acol + 1][arow] = a4n.y;
            As[nb][acol + 2][arow] = a4n.z;
            As[nb][acol + 3][arow] = a4n.w;
            *(float4*)&Bs[nb][brow][bcol] = b4n;
            __syncthreads();
            buf = nb;
        }
    }

#pragma unroll
    for (int i = 0; i < 8; i++) {
        int row = (i < 4) ? (ty * 4 + i) : (64 + ty * 4 + (i - 4));
#pragma unroll
        for (int jh = 0; jh < 2; jh++) {
            int col = jh * 64 + tx * 4;
            float4 v;
            v.x = acc[i][jh * 4 + 0] + bin[bn + col + 0];
            v.y = acc[i][jh * 4 + 1] + bin[bn + col + 1];
            v.z = acc[i][jh * 4 + 2] + bin[bn + col + 2];
            v.w = acc[i][jh * 4 + 3] + bin[bn + col + 3];
            *(float4*)&g_xp[(size_t)(bm + row) * N + bn + col] = v;
        }
    }
}

// ---------------------------------------------------------------------------
// Recurrent scan (R4 structure; bulk broadcast; deadman waits).
// smem layout (bytes):
//   full[0]@0, full[1]@8 (count 1, tx 8192); empty[0]@16, empty[1]@24 (count 8)
//   OFF_W   : 6144 float4 = 98304 B  weight slice w4[kp][g][up]
//   OFF_H   : h[2][128 kp][8 rows] float2 = 16384 B
//   OFF_RED : red[8 ks][32 lane][13] u64 = 26624 B
//   OFF_STG : stage[2][1024] B (1KB own slice, double buffered)
// ---------------------------------------------------------------------------
#define OFF_W    128
#define OFF_H    98432
#define OFF_RED  114816
#define OFF_STG  141440
#define SCAN_SMEM (OFF_STG + 2048)

__global__ __launch_bounds__(256, 1) __cluster_dims__(8, 1, 1)
void scan_kernel(const float* __restrict__ RK,    // [256, 768]
                 const float* __restrict__ brec)  // [768]
{
    extern __shared__ char smem[];
    const int tid = threadIdx.x;
    const int ut = blockIdx.x;          // cluster rank
    const int bt = blockIdx.y;
    const int u0 = ut * 32;
    const int b0 = bt * 8;

    const uint32_t sbase = smem_u32(smem);
    float4* sW = (float4*)(smem + OFF_W);
    ull* red = (ull*)(smem + OFF_RED);

    // weight fill: w4[kp][g][up] = (W[2kp][u],W[2kp][u+1],W[2kp+1][u],W[2kp+1][u+1])
    for (int i = tid; i < 6144; i += 256) {
        int kp = i / 48;
        int rem = i - kp * 48;
        int g = rem >> 4;
        int up = rem & 15;
        const float* s0 = RK + (size_t)(2 * kp) * G3 + g * 256 + u0 + 2 * up;
        float2 a = *(const float2*)s0;
        float2 b = *(const float2*)(s0 + G3);
        sW[i] = make_float4(a.x, a.y, b.x, b.y);
    }
    // zero buffer 0 of h (h(-1) = 0)
    {
        float4* z = (float4*)(smem + OFF_H);
        for (int i = tid; i < 8192 / 16; i += 256) z[i] = make_float4(0, 0, 0, 0);
    }
    if (tid == 0) {
        mbar_init(sbase + 0, 1);    // full[0]: completes via 1 expect-arrive + 8192B tx
        mbar_init(sbase + 8, 1);    // full[1]
        mbar_init(sbase + 16, 8);   // empty[0]: 8 consumer arrivals
        mbar_init(sbase + 24, 8);   // empty[1]
        asm volatile("fence.mbarrier_init.release.cluster;" ::: "memory");
        mbar_expect(sbase + 8, 8192);   // pre-arm full[1] for the h(0) fill
    }
    __syncthreads();
    CLUSTER_SYNC_();

    const int ks = tid >> 5;        // 0..7 k-split
    const int lane = tid & 31;
    const int bg = lane >> 4;
    const int up = lane & 15;
    const int kp0 = ks * 16;

    const int fb = tid >> 4;        // finalists (tid < 128): local batch row
    const int fu = tid & 15;        // unit pair
    const int bgF = fb >> 2;
    const int rF = fb & 3;

    float2 bzv = make_float2(0, 0), brv = make_float2(0, 0), bhv = make_float2(0, 0);
    if (tid < 128) {
        bzv = *(const float2*)(brec + 0   + u0 + 2 * fu);
        brv = *(const float2*)(brec + 256 + u0 + 2 * fu);
        bhv = *(const float2*)(brec + 512 + u0 + 2 * fu);
    }

    int fullp[2] = {0, 0};
    int emptyp[2] = {0, 1};   // R4-validated parity init
    int dead = 0;

    for (int t = 0; t < T_STEPS; t++) {
        const int v = t & 1;        // buffer holding h(t-1)
        const int w = v ^ 1;        // buffer receiving h(t)

        // prefetch xp(t) before waiting
        float2 mzv, mrv, mhv;
        if (tid < 128) {
            const float* xr = g_xp + ((size_t)(b0 + fb) * T_STEPS + t) * G3;
            mzv = *(const float2*)(xr + 0   + u0 + 2 * fu);
            mrv = *(const float2*)(xr + 256 + u0 + 2 * fu);
            mhv = *(const float2*)(xr + 512 + u0 + 2 * fu);
        }

        if (t > 0) {
            if (!dead && !mbar_try_wait(sbase + v * 8, fullp[v])) dead = 1;
            fullp[v] ^= 1;
        }

        // partial GEMM over this thread's 16 unit-pairs of k
        ull acc[4][3];
#pragma unroll
        for (int r = 0; r < 4; r++)
#pragma unroll
            for (int g = 0; g < 3; g++) acc[r][g] = 0ull;

        const char* hbuf = smem + OFF_H + v * 8192;
#pragma unroll 4
        for (int kp = kp0; kp < kp0 + 16; kp++) {
            float4 hA = *(const float4*)(hbuf + kp * 64 + bg * 32);
            float4 hB = *(const float4*)(hbuf + kp * 64 + bg * 32 + 16);
            ull h0[4], h1[4];
            h0[0] = p1(hA.x); h1[0] = p1(hA.y);
            h0[1] = p1(hA.z); h1[1] = p1(hA.w);
            h0[2] = p1(hB.x); h1[2] = p1(hB.y);
            h0[3] = p1(hB.z); h1[3] = p1(hB.w);
#pragma unroll
            for (int g = 0; g < 3; g++) {
                float4 wv = sW[kp * 48 + g * 16 + up];
                ull w01 = p2(wv.x, wv.y);
                ull w23 = p2(wv.z, wv.w);
#pragma unroll
                for (int r = 0; r < 4; r++) {
                    fma2(acc[r][g], h0[r], w01);
                    fma2(acc[r][g], h1[r], w23);
                }
            }
        }

        // own h_prev (read buffer v before releasing it)
        float2 hp = make_float2(0, 0);
        if (tid < 128)
            hp = *(const float2*)(hbuf + ((ut * 16 + fu) * 8 + fb) * 8);

        {
            ull* my = red + (size_t)(ks * 32 + lane) * 13;
#pragma unroll
            for (int g = 0; g < 3; g++)
#pragma unroll
                for (int r = 0; r < 4; r++)
                    my[g * 4 + r] = acc[r][g];
        }
        __syncthreads();

        // buffer v fully consumed: arm its next fill, release it cluster-wide
        if (tid == 0 && t <= T_STEPS - 3) {
            mbar_expect(sbase + v * 8, 8192);      // h(t+1) -> buffer v
            uint32_t emb = sbase + 16 + v * 8;
#pragma unroll
            for (int c = 0; c < 8; c++)
                mbar_arrive_remote(mapa_u32(emb, c));
        }

        if (tid < 128) {
            ull s[3];
#pragma unroll
            for (int g = 0; g < 3; g++) {
                ull a = red[(size_t)(bgF * 16 + fu) * 13 + g * 4 + rF];
#pragma unroll
                for (int k2 = 1; k2 < 8; k2++)
                    add2(a, red[(size_t)(k2 * 32 + bgF * 16 + fu) * 13 + g * 4 + rF]);
                s[g] = a;
            }
            float2 az = unp2(s[0]);
            float2 ar = unp2(s[1]);
            float2 ah = unp2(s[2]);

            float z0 = sigm_(mzv.x + az.x + bzv.x);
            float r0 = sigm_(mrv.x + ar.x + brv.x);
            float c0 = tanh_(mhv.x + r0 * (ah.x + bhv.x));
            float hn0 = z0 * hp.x + (1.f - z0) * c0;

            float z1 = sigm_(mzv.y + az.y + bzv.y);
            float r1 = sigm_(mrv.y + ar.y + brv.y);
            float c1 = tanh_(mhv.y + r1 * (ah.y + bhv.y));
            float hn1 = z1 * hp.y + (1.f - z1) * c1;

            *(float2*)(g_hseq + ((size_t)(b0 + fb) * T_STEPS + t) * UNITS + u0 + 2 * fu)
                = make_float2(hn0, hn1);

            // stage h(t) locally; stage[w] reuse is guarded by empty[w]:
            // delivery of the step t-2 bulk (observed by peers at t-1, whose
            // empty arrives we now hold) implies its source read completed.
            if (t <= T_STEPS - 2) {
                if (!dead && !mbar_try_wait(sbase + 16 + w * 8, emptyp[w])) dead = 1;
                emptyp[w] ^= 1;
                *(float2*)(smem + OFF_STG + w * 1024 + fu * 64 + fb * 8)
                    = make_float2(hn0, hn1);
            }
        }

        if (t <= T_STEPS - 2) {
            __syncthreads();               // stage writes complete, waits done
            if (tid == 0) {
                asm volatile("fence.proxy.async.shared::cta;" ::: "memory");
                uint32_t src = sbase + OFF_STG + w * 1024;
                uint32_t dl  = sbase + OFF_H + w * 8192 + ut * 1024;
                uint32_t ml  = sbase + w * 8;   // peer's full[w]
#pragma unroll
                for (int c = 0; c < 8; c++)
                    bulk_dsmem(mapa_u32(dl, c), src, 1024, mapa_u32(ml, c));
            }
        }
    }
    CLUSTER_SYNC_();
}

// ---------------------------------------------------------------------------
__global__ void copy_out_kernel(float* __restrict__ out) {
    int i = blockIdx.x * 256 + threadIdx.x;
    int b = i >> 8;
    int u = i & 255;
    out[i] = g_hseq[((size_t)b * T_STEPS + (T_STEPS - 1)) * UNITS + u];
}

// ---------------------------------------------------------------------------
extern "C" void kernel_launch(void* const* d_in, const int* in_sizes, int n_in,
                              void* d_out, int out_size) {
    (void)in_sizes; (void)n_in; (void)out_size;
    const float* x     = (const float*)d_in[0];
    const float* k0    = (const float*)d_in[1];
    const float* rk0   = (const float*)d_in[2];
    const float* b0    = (const float*)d_in[3];
    const float* kern  = (const float*)d_in[4];
    const float* rkern = (const float*)d_in[5];
    const float* bias  = (const float*)d_in[6];
    float* out = (float*)d_out;

    cudaFuncSetAttribute(scan_kernel,
        cudaFuncAttributeMaxDynamicSharedMemorySize, SCAN_SMEM);

    dim3 ggrid(G3 / 128, MROWS / 128);
    dim3 sgrid(8, 16);

    gemm_kernel<<<ggrid, 256>>>(x, k0, b0, 1);
    scan_kernel<<<sgrid, 256, SCAN_SMEM>>>(rk0, b0 + G3);

    for (int l = 0; l < 3; l++) {
        gemm_kernel<<<ggrid, 256>>>(nullptr, kern + (size_t)l * 256 * G3,
                                    bias + (size_t)l * 2 * G3, 0);
        scan_kernel<<<sgrid, 256, SCAN_SMEM>>>(rkern + (size_t)l * 256 * G3,
                                    bias + (size_t)l * 2 * G3 + G3);
    }

    copy_out_kernel<<<BATCH, 256>>>(out);
}

// round 14
// speedup vs baseline: 2.2082x; 1.0002x over previous
#include <cuda_runtime.h>
#include <cstdint>
#include <cstddef>

// ---------------------------------------------------------------------------
// GRU stack: 4 layers (256 -> 256), B=128, T=384, reset_after=True (Keras).
// Phase A (per layer): xp = X @ W + b_in   (fp32 GEMM, scalar FFMA, dbl-buffer)
// Phase B (per layer): persistent scan, 8-CTA clusters per batch tile.
//   h exchanged via 8 x 1KB s2s bulk copies into a DEPTH-4 ring buffer:
//   the producer-side empty wait has slack 3 and never blocks, leaving one
//   blocking rendezvous (the data-dependent full wait) per step.
// ---------------------------------------------------------------------------

#define BATCH   128
#define T_STEPS 384
#define UNITS   256
#define G3      768
#define MROWS   (BATCH * T_STEPS)   // 49152

__device__ float g_xp[MROWS * G3];      // [B*T, 768] input projections
__device__ float g_hseq[MROWS * UNITS]; // [B*T, 256] hidden sequence

// ---------------------------------------------------------------------------
typedef unsigned long long ull;

__device__ __forceinline__ ull p2(float x, float y) {
    ull d; asm("mov.b64 %0, {%1, %2};" : "=l"(d) : "f"(x), "f"(y)); return d;
}
__device__ __forceinline__ ull p1(float x) {
    ull d; asm("mov.b64 %0, {%1, %1};" : "=l"(d) : "f"(x)); return d;
}
__device__ __forceinline__ void fma2(ull& acc, ull a, ull b) {
    asm("fma.rn.f32x2 %0, %1, %2, %0;" : "+l"(acc) : "l"(a), "l"(b));
}
__device__ __forceinline__ void add2(ull& acc, ull a) {
    asm("add.rn.f32x2 %0, %1, %0;" : "+l"(acc) : "l"(a));
}
__device__ __forceinline__ float2 unp2(ull d) {
    float2 v; asm("mov.b64 {%0, %1}, %2;" : "=f"(v.x), "=f"(v.y) : "l"(d)); return v;
}

// ---------------------------------------------------------------------------
__device__ __forceinline__ uint32_t smem_u32(const void* p) {
    uint32_t a;
    asm("{ .reg .u64 t; cvta.to.shared.u64 t, %1; cvt.u32.u64 %0, t; }"
        : "=r"(a) : "l"(p));
    return a;
}
__device__ __forceinline__ uint32_t mapa_u32(uint32_t a, uint32_t rank) {
    uint32_t r;
    asm("mapa.shared::cluster.u32 %0, %1, %2;" : "=r"(r) : "r"(a), "r"(rank));
    return r;
}
__device__ __forceinline__ void mbar_init(uint32_t a, uint32_t cnt) {
    asm volatile("mbarrier.init.shared.b64 [%0], %1;" :: "r"(a), "r"(cnt) : "memory");
}
__device__ __forceinline__ void mbar_expect(uint32_t a, uint32_t bytes) {
    asm volatile("mbarrier.arrive.expect_tx.shared.b64 _, [%0], %1;"
                 :: "r"(a), "r"(bytes) : "memory");
}
__device__ __forceinline__ void mbar_arrive_remote(uint32_t a) {
    asm volatile("mbarrier.arrive.shared::cluster.b64 _, [%0];" :: "r"(a) : "memory");
}
// deadman wait: pure fast spin, bounded; wedge -> garbage fast, never a hang.
__device__ __forceinline__ bool mbar_try_wait(uint32_t a, int parity) {
    unsigned ok = 0;
    for (int i = 0; i < 20000; i++) {
        asm volatile(
            "{\n\t.reg .pred P;\n\t"
            "mbarrier.try_wait.parity.acquire.cluster.shared::cta.b64 P, [%1], %2;\n\t"
            "selp.u32 %0, 1, 0, P;\n\t}"
            : "=r"(ok) : "r"(a), "r"((unsigned)parity) : "memory");
        if (ok) return true;
    }
    return false;
}
// s2s bulk: local SMEM -> peer CTA SMEM, complete_tx (bytes) on peer's mbar.
__device__ __forceinline__ void bulk_dsmem(uint32_t dst_cluster, uint32_t src_cta,
                                           uint32_t bytes, uint32_t rmbar_cluster) {
    asm volatile(
        "cp.async.bulk.shared::cluster.shared::cta.mbarrier::complete_tx::bytes "
        "[%0], [%1], %2, [%3];"
        :: "r"(dst_cluster), "r"(src_cta), "r"(bytes), "r"(rmbar_cluster) : "memory");
}
#define CLUSTER_SYNC_() do {                                          \
    asm volatile("barrier.cluster.arrive.aligned;" ::: "memory");     \
    asm volatile("barrier.cluster.wait.aligned;" ::: "memory");       \
} while (0)

__device__ __forceinline__ float sigm_(float x) {
    return 1.f / (1.f + __expf(-x));
}
__device__ __forceinline__ float tanh_(float x) {
    float s = 1.f / (1.f + __expf(-2.f * x));
    return 2.f * s - 1.f;
}

// ---------------------------------------------------------------------------
// SGEMM: C[M=49152, N=768] = A[M,256] @ W[256,768] + bias_in[768]
// (Proven R2/R5 version: 359us, fma=67.5%, regs=125.)
// ---------------------------------------------------------------------------
__global__ __launch_bounds__(256, 2) void gemm_kernel(
    const float* __restrict__ X,
    const float* __restrict__ W,
    const float* __restrict__ bin,
    int use_x)
{
    const int K = 256, N = G3;
    const float* A = use_x ? X : g_hseq;

    __shared__ float As[2][8][128];
    __shared__ float Bs[2][8][128];

    int tid = threadIdx.x;
    int tx = tid & 15;
    int ty = tid >> 4;
    int bm = blockIdx.y * 128;
    int bn = blockIdx.x * 128;

    float acc[8][8];
#pragma unroll
    for (int i = 0; i < 8; i++)
#pragma unroll
        for (int j = 0; j < 8; j++) acc[i][j] = 0.f;

    int arow = tid >> 1;
    int acol = (tid & 1) * 4;
    int brow = tid >> 5;
    int bcol = (tid & 31) * 4;

    const float* Ap = A + (size_t)(bm + arow) * K + acol;
    const float* Wp = W + (size_t)brow * N + bn + bcol;

    {
        float4 a4 = *(const float4*)(Ap);
        float4 b4 = *(const float4*)(Wp);
        As[0][acol + 0][arow] = a4.x;
        As[0][acol + 1][arow] = a4.y;
        As[0][acol + 2][arow] = a4.z;
        As[0][acol + 3][arow] = a4.w;
        *(float4*)&Bs[0][brow][bcol] = b4;
    }
    __syncthreads();

    int buf = 0;
    for (int k0 = 8; k0 <= K; k0 += 8) {
        float4 a4n, b4n;
        if (k0 < K) {
            a4n = *(const float4*)(Ap + k0);
            b4n = *(const float4*)(Wp + (size_t)k0 * N);
        }
#pragma unroll
        for (int kk = 0; kk < 8; kk++) {
            float ra[8], rb[8];
            *(float4*)(ra)     = *(const float4*)&As[buf][kk][ty * 4];
            *(float4*)(ra + 4) = *(const float4*)&As[buf][kk][64 + ty * 4];
            *(float4*)(rb)     = *(const float4*)&Bs[buf][kk][tx * 4];
            *(float4*)(rb + 4) = *(const float4*)&Bs[buf][kk][64 + tx * 4];
#pragma unroll
            for (int i = 0; i < 8; i++)
#pragma unroll
                for (int j = 0; j < 8; j++)
                    acc[i][j] += ra[i] * rb[j];
        }
        if (k0 < K) {
            int nb = buf ^ 1;
            As[nb][acol + 0][arow] = a4n.x;
            As[nb][acol + 1][arow] = a4n.y;
            As[nb][acol + 2][arow] = a4n.z;
            As[nb][acol + 3][arow] = a4n.w;
            *(float4*)&Bs[nb][brow][bcol] = b4n;
            __syncthreads();
            buf = nb;
        }
    }

#pragma unroll
    for (int i = 0; i < 8; i++) {
        int row = (i < 4) ? (ty * 4 + i) : (64 + ty * 4 + (i - 4));
#pragma unroll
        for (int jh = 0; jh < 2; jh++) {
            int col = jh * 64 + tx * 4;
            float4 v;
            v.x = acc[i][jh * 4 + 0] + bin[bn + col + 0];
            v.y = acc[i][jh * 4 + 1] + bin[bn + col + 1];
            v.z = acc[i][jh * 4 + 2] + bin[bn + col + 2];
            v.w = acc[i][jh * 4 + 3] + bin[bn + col + 3];
            *(float4*)&g_xp[(size_t)(bm + row) * N + bn + col] = v;
        }
    }
}

// ---------------------------------------------------------------------------
// Recurrent scan, depth-4 h ring.
// smem layout (bytes):
//   full[s]@ s*8 (s=0..3, count 1, tx 8192); empty[s]@ 32+s*8 (count 8)
//   OFF_W   : 6144 float4 = 98304 B  weight slice w4[kp][g][up]
//   OFF_H   : h[4][128 kp][8 rows] float2 = 32768 B
//   OFF_RED : red[8 ks][32 lane][13] u64 = 26624 B
//   OFF_STG : stage[4][1024] B
// Slot map: h(t) -> slot t&3. Slot 3 zero-initialized (holds h(-1)).
// full[s] fill #n waited with parity n&1; all 4 pre-armed at init, re-armed
// at consumption (3 steps ahead of the fill; peer skew < 1 step).
// empty[s]: released at consumption; producer wait (t>=4 only) has slack 3.
// ---------------------------------------------------------------------------
#define OFF_W    128
#define OFF_H    98432
#define OFF_RED  131200
#define OFF_STG  157824
#define SCAN_SMEM (OFF_STG + 4096)   // 161920

__global__ __launch_bounds__(256, 1) __cluster_dims__(8, 1, 1)
void scan_kernel(const float* __restrict__ RK,    // [256, 768]
                 const float* __restrict__ brec)  // [768]
{
    extern __shared__ char smem[];
    const int tid = threadIdx.x;
    const int ut = blockIdx.x;          // cluster rank
    const int bt = blockIdx.y;
    const int u0 = ut * 32;
    const int b0 = bt * 8;

    const uint32_t sbase = smem_u32(smem);
    float4* sW = (float4*)(smem + OFF_W);
    ull* red = (ull*)(smem + OFF_RED);

    // weight fill: w4[kp][g][up] = (W[2kp][u],W[2kp][u+1],W[2kp+1][u],W[2kp+1][u+1])
    for (int i = tid; i < 6144; i += 256) {
        int kp = i / 48;
        int rem = i - kp * 48;
        int g = rem >> 4;
        int up = rem & 15;
        const float* s0 = RK + (size_t)(2 * kp) * G3 + g * 256 + u0 + 2 * up;
        float2 a = *(const float2*)s0;
        float2 b = *(const float2*)(s0 + G3);
        sW[i] = make_float4(a.x, a.y, b.x, b.y);
    }
    // zero the whole h ring (slot 3 = h(-1) must be 0)
    {
        float4* z = (float4*)(smem + OFF_H);
        for (int i = tid; i < 32768 / 16; i += 256) z[i] = make_float4(0, 0, 0, 0);
    }
    if (tid == 0) {
#pragma unroll
        for (int s = 0; s < 4; s++) {
            mbar_init(sbase + s * 8, 1);        // full[s]
            mbar_init(sbase + 32 + s * 8, 8);   // empty[s]
        }
        asm volatile("fence.mbarrier_init.release.cluster;" ::: "memory");
        // pre-arm all four full barriers for their first fills (h(0..3))
#pragma unroll
        for (int s = 0; s < 4; s++) mbar_expect(sbase + s * 8, 8192);
    }
    __syncthreads();
    CLUSTER_SYNC_();

    const int ks = tid >> 5;        // 0..7 k-split
    const int lane = tid & 31;
    const int bg = lane >> 4;
    const int up = lane & 15;
    const int kp0 = ks * 16;

    const int fb = tid >> 4;        // finalists (tid < 128): local batch row
    const int fu = tid & 15;        // unit pair
    const int bgF = fb >> 2;
    const int rF = fb & 3;

    float2 bzv = make_float2(0, 0), brv = make_float2(0, 0), bhv = make_float2(0, 0);
    if (tid < 128) {
        bzv = *(const float2*)(brec + 0   + u0 + 2 * fu);
        brv = *(const float2*)(brec + 256 + u0 + 2 * fu);
        bhv = *(const float2*)(brec + 512 + u0 + 2 * fu);
    }

    int dead = 0;

    for (int t = 0; t < T_STEPS; t++) {
        const int si = (t + 3) & 3;     // slot holding h(t-1)  ((t-1)&3)
        const int so = t & 3;           // slot receiving h(t)

        // prefetch xp(t) before waiting
        float2 mzv, mrv, mhv;
        if (tid < 128) {
            const float* xr = g_xp + ((size_t)(b0 + fb) * T_STEPS + t) * G3;
            mzv = *(const float2*)(xr + 0   + u0 + 2 * fu);
            mrv = *(const float2*)(xr + 256 + u0 + 2 * fu);
            mhv = *(const float2*)(xr + 512 + u0 + 2 * fu);
        }

        // full wait for h(t-1): fill #n of slot si, parity n&1
        if (t > 0) {
            int par = ((t - 1) >> 2) & 1;
            if (!dead && !mbar_try_wait(sbase + si * 8, par)) dead = 1;
        }

        // partial GEMM over this thread's 16 unit-pairs of k
        ull acc[4][3];
#pragma unroll
        for (int r = 0; r < 4; r++)
#pragma unroll
            for (int g = 0; g < 3; g++) acc[r][g] = 0ull;

        const char* hbuf = smem + OFF_H + si * 8192;
#pragma unroll 4
        for (int kp = kp0; kp < kp0 + 16; kp++) {
            float4 hA = *(const float4*)(hbuf + kp * 64 + bg * 32);
            float4 hB = *(const float4*)(hbuf + kp * 64 + bg * 32 + 16);
            ull h0[4], h1[4];
            h0[0] = p1(hA.x); h1[0] = p1(hA.y);
            h0[1] = p1(hA.z); h1[1] = p1(hA.w);
            h0[2] = p1(hB.x); h1[2] = p1(hB.y);
            h0[3] = p1(hB.z); h1[3] = p1(hB.w);
#pragma unroll
            for (int g = 0; g < 3; g++) {
                float4 wv = sW[kp * 48 + g * 16 + up];
                ull w01 = p2(wv.x, wv.y);
                ull w23 = p2(wv.z, wv.w);
#pragma unroll
                for (int r = 0; r < 4; r++) {
                    fma2(acc[r][g], h0[r], w01);
                    fma2(acc[r][g], h1[r], w23);
                }
            }
        }

        // own h_prev (read slot si before releasing it)
        float2 hp = make_float2(0, 0);
        if (tid < 128)
            hp = *(const float2*)(hbuf + ((ut * 16 + fu) * 8 + fb) * 8);

        {
            ull* my = red + (size_t)(ks * 32 + lane) * 13;
#pragma unroll
            for (int g = 0; g < 3; g++)
#pragma unroll
                for (int r = 0; r < 4; r++)
                    my[g * 4 + r] = acc[r][g];
        }
        __syncthreads();

        // slot si fully consumed: re-arm it for its fill at t+3, release empty.
        // t>=1 only (slot 3's zero-state at t=0 needs no arm/release; a t=0 arm
        // would double-arm and deadlock, a t=0 release would shift parity).
        if (tid == 0 && t >= 1 && t <= T_STEPS - 5) {
            mbar_expect(sbase + si * 8, 8192);
            uint32_t emb = sbase + 32 + si * 8;
#pragma unroll
            for (int c = 0; c < 8; c++)
                mbar_arrive_remote(mapa_u32(emb, c));
        }

        if (tid < 128) {
            ull s[3];
#pragma unroll
            for (int g = 0; g < 3; g++) {
                ull a = red[(size_t)(bgF * 16 + fu) * 13 + g * 4 + rF];
#pragma unroll
                for (int k2 = 1; k2 < 8; k2++)
                    add2(a, red[(size_t)(k2 * 32 + bgF * 16 + fu) * 13 + g * 4 + rF]);
                s[g] = a;
            }
            float2 az = unp2(s[0]);
            float2 ar = unp2(s[1]);
            float2 ah = unp2(s[2]);

            float z0 = sigm_(mzv.x + az.x + bzv.x);
            float r0 = sigm_(mrv.x + ar.x + brv.x);
            float c0 = tanh_(mhv.x + r0 * (ah.x + bhv.x));
            float hn0 = z0 * hp.x + (1.f - z0) * c0;

            float z1 = sigm_(mzv.y + az.y + bzv.y);
            float r1 = sigm_(mrv.y + ar.y + brv.y);
            float c1 = tanh_(mhv.y + r1 * (ah.y + bhv.y));
            float hn1 = z1 * hp.y + (1.f - z1) * c1;

            *(float2*)(g_hseq + ((size_t)(b0 + fb) * T_STEPS + t) * UNITS + u0 + 2 * fu)
                = make_float2(hn0, hn1);

            // stage h(t); slot so's previous occupant h(t-4) must be consumed:
            // slack-3 wait, normally already satisfied (fast path).
            if (t <= T_STEPS - 2) {
                if (t >= 4) {
                    int par = ((t >> 2) - 1) & 1;
                    if (!dead && !mbar_try_wait(sbase + 32 + so * 8, par)) dead = 1;
                }
                *(float2*)(smem + OFF_STG + so * 1024 + fu * 64 + fb * 8)
                    = make_float2(hn0, hn1);
            }
        }

        if (t <= T_STEPS - 2) {
            __syncthreads();               // stage writes + empty waits done
            if (tid == 0) {
                asm volatile("fence.proxy.async.shared::cta;" ::: "memory");
                uint32_t src = sbase + OFF_STG + so * 1024;
                uint32_t dl  = sbase + OFF_H + so * 8192 + ut * 1024;
                uint32_t ml  = sbase + so * 8;   // peer's full[so]
#pragma unroll
                for (int c = 0; c < 8; c++)
                    bulk_dsmem(mapa_u32(dl, c), src, 1024, mapa_u32(ml, c));
            }
        }
    }
    CLUSTER_SYNC_();
}

// ---------------------------------------------------------------------------
__global__ void copy_out_kernel(float* __restrict__ out) {
    int i = blockIdx.x * 256 + threadIdx.x;
    int b = i >> 8;
    int u = i & 255;
    out[i] = g_hseq[((size_t)b * T_STEPS + (T_STEPS - 1)) * UNITS + u];
}

// ---------------------------------------------------------------------------
extern "C" void kernel_launch(void* const* d_in, const int* in_sizes, int n_in,
                              void* d_out, int out_size) {
    (void)in_sizes; (void)n_in; (void)out_size;
    const float* x     = (const float*)d_in[0];
    const float* k0    = (const float*)d_in[1];
    const float* rk0   = (const float*)d_in[2];
    const float* b0    = (const float*)d_in[3];
    const float* kern  = (const float*)d_in[4];
    const float* rkern = (const float*)d_in[5];
    const float* bias  = (const float*)d_in[6];
    float* out = (float*)d_out;

    cudaFuncSetAttribute(scan_kernel,
        cudaFuncAttributeMaxDynamicSharedMemorySize, SCAN_SMEM);

    dim3 ggrid(G3 / 128, MROWS / 128);
    dim3 sgrid(8, 16);

    gemm_kernel<<<ggrid, 256>>>(x, k0, b0, 1);
    scan_kernel<<<sgrid, 256, SCAN_SMEM>>>(rk0, b0 + G3);

    for (int l = 0; l < 3; l++) {
        gemm_kernel<<<ggrid, 256>>>(nullptr, kern + (size_t)l * 256 * G3,
                                    bias + (size_t)l * 2 * G3, 0);
        scan_kernel<<<sgrid, 256, SCAN_SMEM>>>(rkern + (size_t)l * 256 * G3,
                                    bias + (size_t)l * 2 * G3 + G3);
    }

    copy_out_kernel<<<BATCH, 256>>>(out);
}